// round 2
// baseline (speedup 1.0000x reference)
#include <cuda_runtime.h>
#include <math_constants.h>

// VerticalLinePool: out[b,c,h,w] = max_{h' >= h} x[b,c,h',w]
// x shape (8, 128, 256, 256) fp32, NCHW contiguous.
// One thread per (b,c, w/4) float4-column; scan h bottom-up with running max.
// Round 2: explicit 8-wide load batching (force MLP=8 in registers) +
// evict-first streaming cache hints on both the load and store paths.

#define H_DIM 256
#define W4    64                 // W / 4 float4s per row
#define NITEMS (8 * 128 * W4)    // 65536 float4-columns
#define UNROLL 8

__global__ __launch_bounds__(64) void vertical_line_pool_kernel(
    const float4* __restrict__ x, float4* __restrict__ out)
{
    unsigned int t = blockIdx.x * 64u + threadIdx.x;   // 0 .. NITEMS-1
    unsigned int bc = t >> 6;          // which (b,c) plane
    unsigned int w4 = t & 63u;         // which float4 within a row

    size_t base = (size_t)bc * (H_DIM * W4) + w4;      // element (h=0) of this column
    const float4* __restrict__ xp = x + base;
    float4* __restrict__ op = out + base;

    float4 m = make_float4(-CUDART_INF_F, -CUDART_INF_F, -CUDART_INF_F, -CUDART_INF_F);

    // Scan from bottom (h = H-1) to top (h = 0) in batches of 8.
    // Phase 1 of each batch: 8 independent LDG.E.128 issued back-to-back
    // (explicit register array defeats ptxas register-pressure collapse).
    // Phase 2: serial fmax chain + 8 STG.E.128.
    for (int h0 = H_DIM - 1; h0 >= 0; h0 -= UNROLL) {
        float4 v[UNROLL];
        #pragma unroll
        for (int i = 0; i < UNROLL; ++i) {
            v[i] = __ldcs(&xp[(size_t)(h0 - i) * W4]);   // evict-first load
        }
        #pragma unroll
        for (int i = 0; i < UNROLL; ++i) {
            m.x = fmaxf(m.x, v[i].x);
            m.y = fmaxf(m.y, v[i].y);
            m.z = fmaxf(m.z, v[i].z);
            m.w = fmaxf(m.w, v[i].w);
            __stcs(&op[(size_t)(h0 - i) * W4], m);       // evict-first store
        }
    }
}

extern "C" void kernel_launch(void* const* d_in, const int* in_sizes, int n_in,
                              void* d_out, int out_size)
{
    const float4* x = (const float4*)d_in[0];
    float4* out = (float4*)d_out;

    dim3 grid(NITEMS / 64);   // 1024 blocks -> ~6.9/SM, single wave, 1.2% imbalance
    dim3 block(64);
    vertical_line_pool_kernel<<<grid, block>>>(x, out);
}